// round 3
// baseline (speedup 1.0000x reference)
#include <cuda_runtime.h>
#include <cuda_bf16.h>

#define BB 16
#define CC 16
#define OO 16
#define NN 256
#define NPAIRS 136   // 16*17/2 tile pairs (Ti <= Tj)

// Scratch (no allocations allowed -> __device__ globals), ~6 MB total
__device__ float d_rowsum[BB*CC*NN*2];
__device__ float d_colsum[BB*CC*NN*2];
__device__ float d_diag  [BB*CC*NN*2];
__device__ float d_v1    [BB*CC*2];
__device__ float d_Dd    [BB*OO*NN*2];
__device__ float d_Rt    [BB*OO*NN*2];
__device__ float d_Ct    [BB*OO*NN*2];
__device__ float d_GH    [BB*OO*4];

// ---------------------------------------------------------------------------
// Phase 1: per (b,c) compute row_sum[i], col_sum[j], diag[i], and
//          v1 = mean(diag) + total_sum. One coalesced pass over the input.
// ---------------------------------------------------------------------------
__global__ __launch_bounds__(256) void reduce_kernel(const float* __restrict__ in)
{
    int bc  = blockIdx.x;                       // b*CC + c
    const float* base = in + (size_t)bc * NN * NN * 2;
    int tid = threadIdx.x, w = tid >> 5, l = tid & 31;

    __shared__ float2 colsh[NN];
    __shared__ float2 rowsh[NN];
    __shared__ float2 diagrow[NN];
    __shared__ float  tot[2];
    __shared__ float  dsum[2];

    colsh[tid] = make_float2(0.f, 0.f);
    if (tid < 2) { tot[tid] = 0.f; dsum[tid] = 0.f; }
    __syncthreads();

    float2 colacc[8];
    #pragma unroll
    for (int q = 0; q < 8; q++) colacc[q] = make_float2(0.f, 0.f);
    float2 laneTot = make_float2(0.f, 0.f);

    // warp w handles rows {w, w+8, ...}; lane covers 8 columns via float4 loads
    for (int i = w; i < NN; i += 8) {
        const float4* row = (const float4*)(base + (size_t)i * NN * 2);
        float2 racc = make_float2(0.f, 0.f);
        #pragma unroll
        for (int s = 0; s < 4; s++) {
            float4 v = row[s * 32 + l];             // columns s*64+2l, s*64+2l+1
            colacc[2*s].x   += v.x; colacc[2*s].y   += v.y;
            colacc[2*s+1].x += v.z; colacc[2*s+1].y += v.w;
            racc.x += v.x + v.z;  racc.y += v.y + v.w;
            int jb = s * 64 + 2 * l;
            if (i == jb)        diagrow[i] = make_float2(v.x, v.y);
            else if (i == jb+1) diagrow[i] = make_float2(v.z, v.w);
        }
        laneTot.x += racc.x; laneTot.y += racc.y;
        #pragma unroll
        for (int off = 16; off > 0; off >>= 1) {
            racc.x += __shfl_down_sync(0xffffffffu, racc.x, off);
            racc.y += __shfl_down_sync(0xffffffffu, racc.y, off);
        }
        if (l == 0) rowsh[i] = racc;
    }

    // column partials -> shared (distinct addresses within a warp)
    #pragma unroll
    for (int s = 0; s < 4; s++) {
        int j0 = s * 64 + 2 * l;
        atomicAdd(&colsh[j0].x,   colacc[2*s].x);
        atomicAdd(&colsh[j0].y,   colacc[2*s].y);
        atomicAdd(&colsh[j0+1].x, colacc[2*s+1].x);
        atomicAdd(&colsh[j0+1].y, colacc[2*s+1].y);
    }
    #pragma unroll
    for (int off = 16; off > 0; off >>= 1) {
        laneTot.x += __shfl_down_sync(0xffffffffu, laneTot.x, off);
        laneTot.y += __shfl_down_sync(0xffffffffu, laneTot.y, off);
    }
    if (l == 0) { atomicAdd(&tot[0], laneTot.x); atomicAdd(&tot[1], laneTot.y); }
    __syncthreads();

    // coalesced global writes of the three per-(b,c) vectors
    float2* rsg = (float2*)d_rowsum + (size_t)bc * NN;
    float2* csg = (float2*)d_colsum + (size_t)bc * NN;
    float2* dgg = (float2*)d_diag   + (size_t)bc * NN;
    rsg[tid] = rowsh[tid];
    csg[tid] = colsh[tid];
    float2 dg = diagrow[tid];
    dgg[tid] = dg;

    #pragma unroll
    for (int off = 16; off > 0; off >>= 1) {
        dg.x += __shfl_down_sync(0xffffffffu, dg.x, off);
        dg.y += __shfl_down_sync(0xffffffffu, dg.y, off);
    }
    if (l == 0) { atomicAdd(&dsum[0], dg.x); atomicAdd(&dsum[1], dg.y); }
    __syncthreads();

    if (tid == 0) {
        d_v1[bc*2+0] = dsum[0] * (1.f / NN) + tot[0];
        d_v1[bc*2+1] = dsum[1] * (1.f / NN) + tot[1];
    }
}

// ---------------------------------------------------------------------------
// Phase 2: per (b,o) mix the reduced vectors over C with weight slots 0..12.
//   Ddiag = W4*diag + W7*col + W10*row    (added on diagonal)
//   Rtot  = W5*diag + W8*col + W11*row    (broadcast over rows, fn of j)
//   Ctot  = W6*diag + W9*col + W12*row    (broadcast over cols, fn of i)
//   G = W0*v1, H = W1*v1  (both class1 calls share weights[...,0:2])
// ---------------------------------------------------------------------------
__global__ __launch_bounds__(256) void mix_kernel(const float* __restrict__ W)
{
    int bo = blockIdx.x; int b = bo >> 4, o = bo & 15;
    int m = threadIdx.x;

    __shared__ float ws[CC][15];
    if (m < CC * 15) { int c = m / 15, s = m % 15; ws[c][s] = W[(c*OO + o)*15 + s]; }
    __syncthreads();

    const float2* dgp = (const float2*)d_diag   + (size_t)b * CC * NN + m;
    const float2* csp = (const float2*)d_colsum + (size_t)b * CC * NN + m;
    const float2* rsp = (const float2*)d_rowsum + (size_t)b * CC * NN + m;

    float2 dacc = make_float2(0.f,0.f), racc = make_float2(0.f,0.f), cacc = make_float2(0.f,0.f);
    #pragma unroll
    for (int c = 0; c < CC; c++) {
        float2 dg = dgp[c * NN];
        float2 cs = csp[c * NN];
        float2 rs = rsp[c * NN];
        float w4 = ws[c][4],  w5 = ws[c][5],  w6 = ws[c][6];
        float w7 = ws[c][7],  w8 = ws[c][8],  w9 = ws[c][9];
        float wA = ws[c][10], wB = ws[c][11], wD = ws[c][12];
        dacc.x += w4*dg.x + w7*cs.x + wA*rs.x;  dacc.y += w4*dg.y + w7*cs.y + wA*rs.y;
        racc.x += w5*dg.x + w8*cs.x + wB*rs.x;  racc.y += w5*dg.y + w8*cs.y + wB*rs.y;
        cacc.x += w6*dg.x + w9*cs.x + wD*rs.x;  cacc.y += w6*dg.y + w9*cs.y + wD*rs.y;
    }
    ((float2*)d_Dd)[(size_t)bo * NN + m] = dacc;
    ((float2*)d_Rt)[(size_t)bo * NN + m] = racc;
    ((float2*)d_Ct)[(size_t)bo * NN + m] = cacc;

    if (m == 0) {
        float gx = 0.f, gy = 0.f, hx = 0.f, hy = 0.f;
        #pragma unroll
        for (int c = 0; c < CC; c++) {
            float vx = d_v1[(b*CC + c)*2], vy = d_v1[(b*CC + c)*2 + 1];
            gx += ws[c][0]*vx; gy += ws[c][0]*vy;
            hx += ws[c][1]*vx; hy += ws[c][1]*vy;
        }
        d_GH[bo*4+0] = gx; d_GH[bo*4+1] = gy; d_GH[bo*4+2] = hx; d_GH[bo*4+3] = hy;
    }
}

// ---------------------------------------------------------------------------
// Phase 3: main pass over compact tile-pair grid (Ti<=Tj). The W13 mix of
// (in + in^T) is SYMMETRIC, so one accumulation serves both the (Ti,Tj) tile
// and its mirror (Tj,Ti); only the bias terms differ. All global accesses
// coalesced; transposes go through padded shared memory (conflict-free).
// ---------------------------------------------------------------------------
__global__ __launch_bounds__(256) void main_kernel(const float* __restrict__ in,
                                                   const float* __restrict__ W,
                                                   float* __restrict__ out)
{
    // unrank linear pair index -> (Ti, Tj) with Ti <= Tj
    int t = blockIdx.x, b = blockIdx.y;
    int Ti = 0;
    while (t >= 16 - Ti) { t -= 16 - Ti; Ti++; }
    int Tj = Ti + t;

    int tid = threadIdx.x;
    int i = tid >> 4, j = tid & 15;

    __shared__ float2 Bs[2][16][17];        // mirror-tile staging (double buffered)
    __shared__ float2 Ts[8][16][17];        // epilogue transpose buffer (8 o at a time)
    __shared__ float  w13[CC][OO];
    __shared__ float2 bR1[OO][16], bC1[OO][16], bR2[OO][16], bC2[OO][16];
    __shared__ float2 gsh[OO], hsh[OO];
    __shared__ float2 ddsh[OO][16];

    {   // weights
        int c = tid >> 4, o = tid & 15;
        w13[c][o] = W[(c*OO + o)*15 + 13];
    }
    {   // bias tiles
        int o = tid >> 4, x = tid & 15;
        const float2* Rt = (const float2*)d_Rt + (size_t)(b*OO + o) * NN;
        const float2* Ct = (const float2*)d_Ct + (size_t)(b*OO + o) * NN;
        bR1[o][x] = Rt[Tj*16 + x];          // Rtot[gj] for own tile
        bC1[o][x] = Ct[Ti*16 + x];          // Ctot[gi] for own tile
        bR2[o][x] = Rt[Ti*16 + x];          // Rtot for mirror tile
        bC2[o][x] = Ct[Tj*16 + x];          // Ctot for mirror tile
        if (Ti == Tj) {
            const float2* Dd = (const float2*)d_Dd + (size_t)(b*OO + o) * NN;
            ddsh[o][x] = Dd[Ti*16 + x];
        }
        if (tid < OO) {
            gsh[tid] = make_float2(d_GH[(b*OO + tid)*4],     d_GH[(b*OO + tid)*4 + 1]);
            hsh[tid] = make_float2(d_GH[(b*OO + tid)*4 + 2], d_GH[(b*OO + tid)*4 + 3]);
        }
    }

    int gi = Ti*16 + i, gj = Tj*16 + j;
    const float2* inb = (const float2*)in + (size_t)b * CC * NN * NN;

    // preload c = 0 (A directly into register, B staged for transpose)
    float2 a = inb[(size_t)gi * NN + gj];
    Bs[0][i][j] = inb[(size_t)(Tj*16 + i) * NN + (Ti*16 + j)];

    float2 acc[OO];
    #pragma unroll
    for (int o = 0; o < OO; o++) acc[o] = make_float2(0.f, 0.f);

    #pragma unroll
    for (int c = 0; c < CC; c++) {
        __syncthreads();
        float2 bb = Bs[c & 1][j][i];
        float2 anext = make_float2(0.f, 0.f);
        if (c + 1 < CC) {
            const float2* pc = inb + (size_t)(c + 1) * NN * NN;
            anext = pc[(size_t)gi * NN + gj];
            Bs[(c + 1) & 1][i][j] = pc[(size_t)(Tj*16 + i) * NN + (Ti*16 + j)];
        }
        float sx = a.x + bb.x, sy = a.y + bb.y;   // symmetric combination
        #pragma unroll
        for (int o = 0; o < OO; o++) {
            float wv = w13[c][o];
            acc[o].x += wv * sx;
            acc[o].y += wv * sy;
        }
        a = anext;
    }

    // epilogue: write own tile + mirror tile (transposed via shared), 8 o/round
    bool diagblk = (Ti == Tj);
    float2* po = (float2*)out + (size_t)b * OO * NN * NN;
    #pragma unroll
    for (int half = 0; half < 2; half++) {
        __syncthreads();
        #pragma unroll
        for (int q = 0; q < 8; q++) Ts[q][i][j] = acc[half*8 + q];
        __syncthreads();
        #pragma unroll
        for (int q = 0; q < 8; q++) {
            int o = half*8 + q;
            float2 tg = Ts[q][j][i];            // value at transposed position
            float2* pout = po + (size_t)o * NN * NN;

            float2 r1;
            r1.x = acc[o].x + gsh[o].x + bR1[o][j].x + bC1[o][i].x;
            r1.y = acc[o].y + gsh[o].y + bR1[o][j].y + bC1[o][i].y;
            if (diagblk && i == j) {
                r1.x += hsh[o].x + ddsh[o][i].x;
                r1.y += hsh[o].y + ddsh[o][i].y;
            }
            pout[(size_t)gi * NN + gj] = r1;

            if (!diagblk) {
                float2 r2;
                r2.x = tg.x + gsh[o].x + bR2[o][j].x + bC2[o][i].x;
                r2.y = tg.y + gsh[o].y + bR2[o][j].y + bC2[o][i].y;
                pout[(size_t)(Tj*16 + i) * NN + (Ti*16 + j)] = r2;
            }
        }
    }
}

// ---------------------------------------------------------------------------
extern "C" void kernel_launch(void* const* d_in, const int* in_sizes, int n_in,
                              void* d_out, int out_size)
{
    const float* in = (const float*)d_in[0];   // (B,C,N,N,2) fp32
    const float* W  = (const float*)d_in[1];   // (C,O,15)    fp32
    float* out = (float*)d_out;                // (B,O,N,N,2) fp32

    reduce_kernel<<<BB * CC, 256>>>(in);
    mix_kernel  <<<BB * OO, 256>>>(W);
    dim3 g(NPAIRS, BB);                        // x=tile pair (Ti<=Tj), y=b
    main_kernel <<<g, 256>>>(in, W, out);
}

// round 5
// speedup vs baseline: 1.0567x; 1.0567x over previous
#include <cuda_runtime.h>
#include <cuda_bf16.h>

#define BB 16
#define CC 16
#define OO 16
#define NN 256
#define NPAIRS 136   // 16*17/2 tile pairs (Ti <= Tj)
#define NSL 8        // row-slices per (b,c) plane in the reduce pass
#define SROWS (NN/NSL)   // 32 rows per slice

// Scratch (no allocations allowed -> __device__ globals)
__device__ float d_rowsum [BB*CC*NN*2];
__device__ float d_colsum [BB*CC*NN*2];
__device__ float d_diag   [BB*CC*NN*2];
__device__ float d_colpart[BB*CC*NSL*NN*2];   // per-slice column partials (4 MB)
__device__ float d_totpart[BB*CC*NSL*2];      // per-slice total partials
__device__ float d_v1     [BB*CC*2];
__device__ float d_Dd     [BB*OO*NN*2];
__device__ float d_Rt     [BB*OO*NN*2];
__device__ float d_Ct     [BB*OO*NN*2];
__device__ float d_GH     [BB*OO*4];

// ---------------------------------------------------------------------------
// Phase 1a: each block reduces a 32-row slice of one (b,c) plane.
//   rowsum + diag: exclusive per slice -> direct coalesced global writes.
//   colsum + total: per-slice partials -> combined in phase 1b.
// grid = BB*CC*NSL = 2048 blocks -> ~14 CTAs/SM, enough MLP to hide DRAM lat.
// ---------------------------------------------------------------------------
__global__ __launch_bounds__(256) void reduce_slice_kernel(const float* __restrict__ in)
{
    int bc = blockIdx.x / NSL;                 // b*CC + c
    int sl = blockIdx.x % NSL;
    int base = sl * SROWS;                     // first row of this slice
    const float* pbase = in + (size_t)bc * NN * NN * 2;
    int tid = threadIdx.x, w = tid >> 5, l = tid & 31;

    __shared__ float2 colsh[NN];
    __shared__ float2 rowsh[SROWS];
    __shared__ float2 diagsh[SROWS];
    __shared__ float  tot[2];

    colsh[tid] = make_float2(0.f, 0.f);
    if (tid < 2) tot[tid] = 0.f;
    __syncthreads();

    float2 colacc[8];
    #pragma unroll
    for (int q = 0; q < 8; q++) colacc[q] = make_float2(0.f, 0.f);
    float2 laneTot = make_float2(0.f, 0.f);

    // warp w handles rows {base+w, base+w+8, base+w+16, base+w+24}
    #pragma unroll
    for (int r = 0; r < SROWS / 8; r++) {
        int i = base + w + r * 8;
        const float4* row = (const float4*)(pbase + (size_t)i * NN * 2);
        float2 racc = make_float2(0.f, 0.f);
        #pragma unroll
        for (int s = 0; s < 4; s++) {
            float4 v = row[s * 32 + l];             // columns s*64+2l, s*64+2l+1
            colacc[2*s].x   += v.x; colacc[2*s].y   += v.y;
            colacc[2*s+1].x += v.z; colacc[2*s+1].y += v.w;
            racc.x += v.x + v.z;  racc.y += v.y + v.w;
            int jb = s * 64 + 2 * l;
            if (i == jb)        diagsh[i - base] = make_float2(v.x, v.y);
            else if (i == jb+1) diagsh[i - base] = make_float2(v.z, v.w);
        }
        laneTot.x += racc.x; laneTot.y += racc.y;
        #pragma unroll
        for (int off = 16; off > 0; off >>= 1) {
            racc.x += __shfl_down_sync(0xffffffffu, racc.x, off);
            racc.y += __shfl_down_sync(0xffffffffu, racc.y, off);
        }
        if (l == 0) rowsh[i - base] = racc;
    }

    // column partials -> shared (distinct addresses within a warp)
    #pragma unroll
    for (int s = 0; s < 4; s++) {
        int j0 = s * 64 + 2 * l;
        atomicAdd(&colsh[j0].x,   colacc[2*s].x);
        atomicAdd(&colsh[j0].y,   colacc[2*s].y);
        atomicAdd(&colsh[j0+1].x, colacc[2*s+1].x);
        atomicAdd(&colsh[j0+1].y, colacc[2*s+1].y);
    }
    #pragma unroll
    for (int off = 16; off > 0; off >>= 1) {
        laneTot.x += __shfl_down_sync(0xffffffffu, laneTot.x, off);
        laneTot.y += __shfl_down_sync(0xffffffffu, laneTot.y, off);
    }
    if (l == 0) { atomicAdd(&tot[0], laneTot.x); atomicAdd(&tot[1], laneTot.y); }
    __syncthreads();

    // coalesced global writes
    ((float2*)d_colpart)[(size_t)blockIdx.x * NN + tid] = colsh[tid];
    if (tid < SROWS) {
        ((float2*)d_rowsum)[(size_t)bc * NN + base + tid] = rowsh[tid];
        ((float2*)d_diag)  [(size_t)bc * NN + base + tid] = diagsh[tid];
    }
    if (tid == 0)
        ((float2*)d_totpart)[blockIdx.x] = make_float2(tot[0], tot[1]);
}

// ---------------------------------------------------------------------------
// Phase 1b: per (b,c) combine the NSL column partials, compute v1.
// ---------------------------------------------------------------------------
__global__ __launch_bounds__(256) void combine_kernel()
{
    int bc = blockIdx.x;
    int tid = threadIdx.x;

    float2 cs = make_float2(0.f, 0.f);
    #pragma unroll
    for (int sl = 0; sl < NSL; sl++) {
        float2 p = ((const float2*)d_colpart)[(size_t)(bc * NSL + sl) * NN + tid];
        cs.x += p.x; cs.y += p.y;
    }
    ((float2*)d_colsum)[(size_t)bc * NN + tid] = cs;

    // dsum: block reduction of diag
    __shared__ float2 red[256];
    red[tid] = ((const float2*)d_diag)[(size_t)bc * NN + tid];
    __syncthreads();
    #pragma unroll
    for (int s = 128; s > 0; s >>= 1) {
        if (tid < s) { red[tid].x += red[tid + s].x; red[tid].y += red[tid + s].y; }
        __syncthreads();
    }
    if (tid == 0) {
        float tx = 0.f, ty = 0.f;
        #pragma unroll
        for (int sl = 0; sl < NSL; sl++) {
            float2 tp = ((const float2*)d_totpart)[bc * NSL + sl];
            tx += tp.x; ty += tp.y;
        }
        d_v1[bc*2+0] = red[0].x * (1.f / NN) + tx;
        d_v1[bc*2+1] = red[0].y * (1.f / NN) + ty;
    }
}

// ---------------------------------------------------------------------------
// Phase 2: per (b,o) mix the reduced vectors over C with weight slots 0..12.
//   Ddiag = W4*diag + W7*col + W10*row    (added on diagonal)
//   Rtot  = W5*diag + W8*col + W11*row    (broadcast over rows, fn of j)
//   Ctot  = W6*diag + W9*col + W12*row    (broadcast over cols, fn of i)
//   G = W0*v1, H = W1*v1  (both class1 calls share weights[...,0:2])
// ---------------------------------------------------------------------------
__global__ __launch_bounds__(256) void mix_kernel(const float* __restrict__ W)
{
    int bo = blockIdx.x; int b = bo >> 4, o = bo & 15;
    int m = threadIdx.x;

    __shared__ float ws[CC][15];
    if (m < CC * 15) { int c = m / 15, s = m % 15; ws[c][s] = W[(c*OO + o)*15 + s]; }
    __syncthreads();

    const float2* dgp = (const float2*)d_diag   + (size_t)b * CC * NN + m;
    const float2* csp = (const float2*)d_colsum + (size_t)b * CC * NN + m;
    const float2* rsp = (const float2*)d_rowsum + (size_t)b * CC * NN + m;

    float2 dacc = make_float2(0.f,0.f), racc = make_float2(0.f,0.f), cacc = make_float2(0.f,0.f);
    #pragma unroll
    for (int c = 0; c < CC; c++) {
        float2 dg = dgp[c * NN];
        float2 cs = csp[c * NN];
        float2 rs = rsp[c * NN];
        float w4 = ws[c][4],  w5 = ws[c][5],  w6 = ws[c][6];
        float w7 = ws[c][7],  w8 = ws[c][8],  w9 = ws[c][9];
        float wA = ws[c][10], wB = ws[c][11], wD = ws[c][12];
        dacc.x += w4*dg.x + w7*cs.x + wA*rs.x;  dacc.y += w4*dg.y + w7*cs.y + wA*rs.y;
        racc.x += w5*dg.x + w8*cs.x + wB*rs.x;  racc.y += w5*dg.y + w8*cs.y + wB*rs.y;
        cacc.x += w6*dg.x + w9*cs.x + wD*rs.x;  cacc.y += w6*dg.y + w9*cs.y + wD*rs.y;
    }
    ((float2*)d_Dd)[(size_t)bo * NN + m] = dacc;
    ((float2*)d_Rt)[(size_t)bo * NN + m] = racc;
    ((float2*)d_Ct)[(size_t)bo * NN + m] = cacc;

    if (m == 0) {
        float gx = 0.f, gy = 0.f, hx = 0.f, hy = 0.f;
        #pragma unroll
        for (int c = 0; c < CC; c++) {
            float vx = d_v1[(b*CC + c)*2], vy = d_v1[(b*CC + c)*2 + 1];
            gx += ws[c][0]*vx; gy += ws[c][0]*vy;
            hx += ws[c][1]*vx; hy += ws[c][1]*vy;
        }
        d_GH[bo*4+0] = gx; d_GH[bo*4+1] = gy; d_GH[bo*4+2] = hx; d_GH[bo*4+3] = hy;
    }
}

// ---------------------------------------------------------------------------
// Phase 3: main pass over compact tile-pair grid (Ti<=Tj). The W13 mix of
// (in + in^T) is SYMMETRIC, so one accumulation serves both the (Ti,Tj) tile
// and its mirror (Tj,Ti); only the bias terms differ. All global accesses
// coalesced; transposes go through padded shared memory (conflict-free).
// ---------------------------------------------------------------------------
__global__ __launch_bounds__(256) void main_kernel(const float* __restrict__ in,
                                                   const float* __restrict__ W,
                                                   float* __restrict__ out)
{
    // unrank linear pair index -> (Ti, Tj) with Ti <= Tj
    int t = blockIdx.x, b = blockIdx.y;
    int Ti = 0;
    while (t >= 16 - Ti) { t -= 16 - Ti; Ti++; }
    int Tj = Ti + t;

    int tid = threadIdx.x;
    int i = tid >> 4, j = tid & 15;

    __shared__ float2 Bs[2][16][17];        // mirror-tile staging (double buffered)
    __shared__ float2 Ts[8][16][17];        // epilogue transpose buffer (8 o at a time)
    __shared__ float  w13[CC][OO];
    __shared__ float2 bR1[OO][16], bC1[OO][16], bR2[OO][16], bC2[OO][16];
    __shared__ float2 gsh[OO], hsh[OO];
    __shared__ float2 ddsh[OO][16];

    {   // weights
        int c = tid >> 4, o = tid & 15;
        w13[c][o] = W[(c*OO + o)*15 + 13];
    }
    {   // bias tiles
        int o = tid >> 4, x = tid & 15;
        const float2* Rt = (const float2*)d_Rt + (size_t)(b*OO + o) * NN;
        const float2* Ct = (const float2*)d_Ct + (size_t)(b*OO + o) * NN;
        bR1[o][x] = Rt[Tj*16 + x];          // Rtot[gj] for own tile
        bC1[o][x] = Ct[Ti*16 + x];          // Ctot[gi] for own tile
        bR2[o][x] = Rt[Ti*16 + x];          // Rtot for mirror tile
        bC2[o][x] = Ct[Tj*16 + x];          // Ctot for mirror tile
        if (Ti == Tj) {
            const float2* Dd = (const float2*)d_Dd + (size_t)(b*OO + o) * NN;
            ddsh[o][x] = Dd[Ti*16 + x];
        }
        if (tid < OO) {
            gsh[tid] = make_float2(d_GH[(b*OO + tid)*4],     d_GH[(b*OO + tid)*4 + 1]);
            hsh[tid] = make_float2(d_GH[(b*OO + tid)*4 + 2], d_GH[(b*OO + tid)*4 + 3]);
        }
    }

    int gi = Ti*16 + i, gj = Tj*16 + j;
    const float2* inb = (const float2*)in + (size_t)b * CC * NN * NN;

    // preload c = 0 (A directly into register, B staged for transpose)
    float2 a = inb[(size_t)gi * NN + gj];
    Bs[0][i][j] = inb[(size_t)(Tj*16 + i) * NN + (Ti*16 + j)];

    float2 acc[OO];
    #pragma unroll
    for (int o = 0; o < OO; o++) acc[o] = make_float2(0.f, 0.f);

    #pragma unroll
    for (int c = 0; c < CC; c++) {
        __syncthreads();
        float2 bb = Bs[c & 1][j][i];
        float2 anext = make_float2(0.f, 0.f);
        if (c + 1 < CC) {
            const float2* pc = inb + (size_t)(c + 1) * NN * NN;
            anext = pc[(size_t)gi * NN + gj];
            Bs[(c + 1) & 1][i][j] = pc[(size_t)(Tj*16 + i) * NN + (Ti*16 + j)];
        }
        float sx = a.x + bb.x, sy = a.y + bb.y;   // symmetric combination
        #pragma unroll
        for (int o = 0; o < OO; o++) {
            float wv = w13[c][o];
            acc[o].x += wv * sx;
            acc[o].y += wv * sy;
        }
        a = anext;
    }

    // epilogue: write own tile + mirror tile (transposed via shared), 8 o/round
    bool diagblk = (Ti == Tj);
    float2* po = (float2*)out + (size_t)b * OO * NN * NN;
    #pragma unroll
    for (int half = 0; half < 2; half++) {
        __syncthreads();
        #pragma unroll
        for (int q = 0; q < 8; q++) Ts[q][i][j] = acc[half*8 + q];
        __syncthreads();
        #pragma unroll
        for (int q = 0; q < 8; q++) {
            int o = half*8 + q;
            float2 tg = Ts[q][j][i];            // value at transposed position
            float2* pout = po + (size_t)o * NN * NN;

            float2 r1;
            r1.x = acc[o].x + gsh[o].x + bR1[o][j].x + bC1[o][i].x;
            r1.y = acc[o].y + gsh[o].y + bR1[o][j].y + bC1[o][i].y;
            if (diagblk && i == j) {
                r1.x += hsh[o].x + ddsh[o][i].x;
                r1.y += hsh[o].y + ddsh[o][i].y;
            }
            pout[(size_t)gi * NN + gj] = r1;

            if (!diagblk) {
                float2 r2;
                r2.x = tg.x + gsh[o].x + bR2[o][j].x + bC2[o][i].x;
                r2.y = tg.y + gsh[o].y + bR2[o][j].y + bC2[o][i].y;
                pout[(size_t)(Tj*16 + i) * NN + (Ti*16 + j)] = r2;
            }
        }
    }
}

// ---------------------------------------------------------------------------
extern "C" void kernel_launch(void* const* d_in, const int* in_sizes, int n_in,
                              void* d_out, int out_size)
{
    const float* in = (const float*)d_in[0];   // (B,C,N,N,2) fp32
    const float* W  = (const float*)d_in[1];   // (C,O,15)    fp32
    float* out = (float*)d_out;                // (B,O,N,N,2) fp32

    reduce_slice_kernel<<<BB * CC * NSL, 256>>>(in);
    combine_kernel     <<<BB * CC, 256>>>();
    mix_kernel         <<<BB * OO, 256>>>(W);
    dim3 g(NPAIRS, BB);                        // x=tile pair (Ti<=Tj), y=b
    main_kernel        <<<g, 256>>>(in, W, out);
}

// round 8
// speedup vs baseline: 1.1126x; 1.0530x over previous
#include <cuda_runtime.h>
#include <cuda_bf16.h>

#define BB 16
#define CC 16
#define OO 16
#define NN 256
#define NPAIRS 136   // 16*17/2 tile pairs (Ti <= Tj)
#define NSL 8        // row-slices per (b,c) plane in the reduce pass
#define SROWS (NN/NSL)   // 32 rows per slice

// Scratch (no allocations allowed -> __device__ globals)
__device__ float d_rowsum [BB*CC*NN*2];
__device__ float d_colsum [BB*CC*NN*2];
__device__ float d_diag   [BB*CC*NN*2];
__device__ float d_colpart[BB*CC*NSL*NN*2];   // per-slice column partials (4 MB)
__device__ float d_v1     [BB*CC*2];
__device__ float d_Dd     [BB*OO*NN*2];
__device__ float d_Rt     [BB*OO*NN*2];
__device__ float d_Ct     [BB*OO*NN*2];
__device__ float d_GH     [BB*OO*4];

// packed f32x2 FMA (Blackwell; ptxas won't auto-fuse from C++)
__device__ __forceinline__ void ffma2(unsigned long long& acc,
                                      unsigned long long s,
                                      unsigned long long w) {
    asm("fma.rn.f32x2 %0, %1, %2, %0;" : "+l"(acc) : "l"(s), "l"(w));
}
__device__ __forceinline__ unsigned long long pack2(float x, float y) {
    unsigned long long r;
    asm("mov.b64 %0, {%1, %2};" : "=l"(r) : "f"(x), "f"(y));
    return r;
}
__device__ __forceinline__ float2 unpack2(unsigned long long v) {
    float2 r;
    asm("mov.b64 {%0, %1}, %2;" : "=f"(r.x), "=f"(r.y) : "l"(v));
    return r;
}

// ---------------------------------------------------------------------------
// Phase 1a: each block reduces a 32-row slice of one (b,c) plane.
// No shfl chains inside the load loop: loads stream, row sums are deferred
// to a shared-memory reduction after the loop.
// ---------------------------------------------------------------------------
__global__ __launch_bounds__(256) void reduce_slice_kernel(const float* __restrict__ in)
{
    int bc = blockIdx.x / NSL;                 // b*CC + c
    int sl = blockIdx.x % NSL;
    int base = sl * SROWS;                     // first row of this slice
    const float* pbase = in + (size_t)bc * NN * NN * 2;
    int tid = threadIdx.x, w = tid >> 5, l = tid & 31;

    __shared__ float2 colsh[NN];
    __shared__ float  rowx[SROWS][33];         // per-lane row partials (padded)
    __shared__ float  rowy[SROWS][33];
    __shared__ float2 diagsh[SROWS];

    colsh[tid] = make_float2(0.f, 0.f);
    __syncthreads();

    float2 colacc[8];
    #pragma unroll
    for (int q = 0; q < 8; q++) colacc[q] = make_float2(0.f, 0.f);

    // warp w handles rows {base+w, base+w+8, base+w+16, base+w+24}
    #pragma unroll
    for (int r = 0; r < SROWS / 8; r++) {
        int i = base + w + r * 8;
        const float4* row = (const float4*)(pbase + (size_t)i * NN * 2);
        float rx = 0.f, ry = 0.f;
        #pragma unroll
        for (int s = 0; s < 4; s++) {
            float4 v = row[s * 32 + l];             // columns s*64+2l, s*64+2l+1
            colacc[2*s].x   += v.x; colacc[2*s].y   += v.y;
            colacc[2*s+1].x += v.z; colacc[2*s+1].y += v.w;
            rx += v.x + v.z;  ry += v.y + v.w;
            int jb = s * 64 + 2 * l;
            if (i == jb)        diagsh[i - base] = make_float2(v.x, v.y);
            else if (i == jb+1) diagsh[i - base] = make_float2(v.z, v.w);
        }
        rowx[w + r*8][l] = rx;                      // defer row reduction
        rowy[w + r*8][l] = ry;
    }

    // column partials -> shared (distinct addresses within a warp)
    #pragma unroll
    for (int s = 0; s < 4; s++) {
        int j0 = s * 64 + 2 * l;
        atomicAdd(&colsh[j0].x,   colacc[2*s].x);
        atomicAdd(&colsh[j0].y,   colacc[2*s].y);
        atomicAdd(&colsh[j0+1].x, colacc[2*s+1].x);
        atomicAdd(&colsh[j0+1].y, colacc[2*s+1].y);
    }
    __syncthreads();

    // coalesced global writes
    ((float2*)d_colpart)[(size_t)blockIdx.x * NN + tid] = colsh[tid];
    if (tid < SROWS) {                              // row sums: thread t owns row t
        float sx = 0.f, sy = 0.f;
        #pragma unroll
        for (int k = 0; k < 32; k++) { sx += rowx[tid][k]; sy += rowy[tid][k]; }
        ((float2*)d_rowsum)[(size_t)bc * NN + base + tid] = make_float2(sx, sy);
        ((float2*)d_diag)  [(size_t)bc * NN + base + tid] = diagsh[tid];
    }
}

// ---------------------------------------------------------------------------
// Phase 1b: per (b,c) combine the NSL column partials; v1 = diag_mean + total,
// where total = sum of colsum (no separate partials needed).
// ---------------------------------------------------------------------------
__global__ __launch_bounds__(256) void combine_kernel()
{
    int bc = blockIdx.x;
    int tid = threadIdx.x;

    float2 cs = make_float2(0.f, 0.f);
    #pragma unroll
    for (int sl = 0; sl < NSL; sl++) {
        float2 p = ((const float2*)d_colpart)[(size_t)(bc * NSL + sl) * NN + tid];
        cs.x += p.x; cs.y += p.y;
    }
    ((float2*)d_colsum)[(size_t)bc * NN + tid] = cs;

    __shared__ float2 red[256];
    __shared__ float2 totsave;

    // total = sum over columns of colsum
    red[tid] = cs;
    __syncthreads();
    #pragma unroll
    for (int s = 128; s > 0; s >>= 1) {
        if (tid < s) { red[tid].x += red[tid + s].x; red[tid].y += red[tid + s].y; }
        __syncthreads();
    }
    if (tid == 0) totsave = red[0];
    __syncthreads();

    // diag sum
    red[tid] = ((const float2*)d_diag)[(size_t)bc * NN + tid];
    __syncthreads();
    #pragma unroll
    for (int s = 128; s > 0; s >>= 1) {
        if (tid < s) { red[tid].x += red[tid + s].x; red[tid].y += red[tid + s].y; }
        __syncthreads();
    }
    if (tid == 0) {
        d_v1[bc*2+0] = red[0].x * (1.f / NN) + totsave.x;
        d_v1[bc*2+1] = red[0].y * (1.f / NN) + totsave.y;
    }
}

// ---------------------------------------------------------------------------
// Phase 2: per (b,o) mix the reduced vectors over C with weight slots 0..12.
// ---------------------------------------------------------------------------
__global__ __launch_bounds__(256) void mix_kernel(const float* __restrict__ W)
{
    int bo = blockIdx.x; int b = bo >> 4, o = bo & 15;
    int m = threadIdx.x;

    __shared__ float ws[CC][15];
    if (m < CC * 15) { int c = m / 15, s = m % 15; ws[c][s] = W[(c*OO + o)*15 + s]; }
    __syncthreads();

    const float2* dgp = (const float2*)d_diag   + (size_t)b * CC * NN + m;
    const float2* csp = (const float2*)d_colsum + (size_t)b * CC * NN + m;
    const float2* rsp = (const float2*)d_rowsum + (size_t)b * CC * NN + m;

    float2 dacc = make_float2(0.f,0.f), racc = make_float2(0.f,0.f), cacc = make_float2(0.f,0.f);
    #pragma unroll
    for (int c = 0; c < CC; c++) {
        float2 dg = dgp[c * NN];
        float2 cs = csp[c * NN];
        float2 rs = rsp[c * NN];
        float w4 = ws[c][4],  w5 = ws[c][5],  w6 = ws[c][6];
        float w7 = ws[c][7],  w8 = ws[c][8],  w9 = ws[c][9];
        float wA = ws[c][10], wB = ws[c][11], wD = ws[c][12];
        dacc.x += w4*dg.x + w7*cs.x + wA*rs.x;  dacc.y += w4*dg.y + w7*cs.y + wA*rs.y;
        racc.x += w5*dg.x + w8*cs.x + wB*rs.x;  racc.y += w5*dg.y + w8*cs.y + wB*rs.y;
        cacc.x += w6*dg.x + w9*cs.x + wD*rs.x;  cacc.y += w6*dg.y + w9*cs.y + wD*rs.y;
    }
    ((float2*)d_Dd)[(size_t)bo * NN + m] = dacc;
    ((float2*)d_Rt)[(size_t)bo * NN + m] = racc;
    ((float2*)d_Ct)[(size_t)bo * NN + m] = cacc;

    if (m == 0) {
        float gx = 0.f, gy = 0.f, hx = 0.f, hy = 0.f;
        #pragma unroll
        for (int c = 0; c < CC; c++) {
            float vx = d_v1[(b*CC + c)*2], vy = d_v1[(b*CC + c)*2 + 1];
            gx += ws[c][0]*vx; gy += ws[c][0]*vy;
            hx += ws[c][1]*vx; hy += ws[c][1]*vy;
        }
        d_GH[bo*4+0] = gx; d_GH[bo*4+1] = gy; d_GH[bo*4+2] = hx; d_GH[bo*4+3] = hy;
    }
}

// ---------------------------------------------------------------------------
// Phase 3: main pass over compact tile-pair grid (Ti<=Tj). Symmetric W13 mix
// serves both (Ti,Tj) and (Tj,Ti). Packed f32x2 FMAs halve the mainloop
// instruction count; triple-buffered mirror staging + 2-deep A prefetch give
// ~2 iterations (~840 cyc) of DRAM latency tolerance.
// ---------------------------------------------------------------------------
__global__ __launch_bounds__(256) void main_kernel(const float* __restrict__ in,
                                                   const float* __restrict__ W,
                                                   float* __restrict__ out)
{
    // unrank linear pair index -> (Ti, Tj) with Ti <= Tj
    int t = blockIdx.x, b = blockIdx.y;
    int Ti = 0;
    while (t >= 16 - Ti) { t -= 16 - Ti; Ti++; }
    int Tj = Ti + t;

    int tid = threadIdx.x;
    int i = tid >> 4, j = tid & 15;

    __shared__ float2 Bs[3][16][17];        // mirror-tile staging (triple buffered)
    __shared__ float2 Ts[8][16][17];        // epilogue transpose buffer (8 o at a time)
    __shared__ unsigned long long w13d[CC][OO];   // (w,w) packed
    __shared__ float2 bR1[OO][16], bC1[OO][16], bR2[OO][16], bC2[OO][16];
    __shared__ float2 hsh[OO];
    __shared__ float2 ddsh[OO][16];

    {   // weights, duplicated into f32x2 lanes
        int c = tid >> 4, o = tid & 15;
        float wv = W[(c*OO + o)*15 + 13];
        w13d[c][o] = pack2(wv, wv);
    }
    {   // bias tiles; fold g (uniform per o) into the row-bias tiles
        int o = tid >> 4, x = tid & 15;
        float2 g = make_float2(d_GH[(b*OO + o)*4], d_GH[(b*OO + o)*4 + 1]);
        const float2* Rt = (const float2*)d_Rt + (size_t)(b*OO + o) * NN;
        const float2* Ct = (const float2*)d_Ct + (size_t)(b*OO + o) * NN;
        float2 r1v = Rt[Tj*16 + x], r2v = Rt[Ti*16 + x];
        bR1[o][x] = make_float2(r1v.x + g.x, r1v.y + g.y);   // Rtot[gj]+g (own tile)
        bC1[o][x] = Ct[Ti*16 + x];                            // Ctot[gi] (own tile)
        bR2[o][x] = make_float2(r2v.x + g.x, r2v.y + g.y);   // mirror tile
        bC2[o][x] = Ct[Tj*16 + x];
        if (Ti == Tj) {
            const float2* Dd = (const float2*)d_Dd + (size_t)(b*OO + o) * NN;
            ddsh[o][x] = Dd[Ti*16 + x];
        }
        if (tid < OO)
            hsh[tid] = make_float2(d_GH[(b*OO + tid)*4 + 2], d_GH[(b*OO + tid)*4 + 3]);
    }

    int gi = Ti*16 + i, gj = Tj*16 + j;
    int mi = Tj*16 + i, mj = Ti*16 + j;     // mirror-tile coordinates
    const float2* inb = (const float2*)in + (size_t)b * CC * NN * NN;

    // preload c = 0,1 (A in registers, B staged for transpose)
    float2 a0 = inb[(size_t)gi * NN + gj];
    float2 a1 = inb[(size_t)NN*NN + (size_t)gi * NN + gj];
    Bs[0][i][j] = inb[(size_t)mi * NN + mj];
    Bs[1][i][j] = inb[(size_t)NN*NN + (size_t)mi * NN + mj];

    unsigned long long acc64[OO];
    #pragma unroll
    for (int o = 0; o < OO; o++) acc64[o] = 0ULL;

    #pragma unroll
    for (int c = 0; c < CC; c++) {
        __syncthreads();
        float2 anext = make_float2(0.f, 0.f);
        if (c + 2 < CC) {
            const float2* pc = inb + (size_t)(c + 2) * NN * NN;
            anext = pc[(size_t)gi * NN + gj];
            Bs[(c + 2) % 3][i][j] = pc[(size_t)mi * NN + mj];
        }
        float2 bb = Bs[c % 3][j][i];
        unsigned long long s64 = pack2(a0.x + bb.x, a0.y + bb.y);
        #pragma unroll
        for (int o = 0; o < OO; o++)
            ffma2(acc64[o], s64, w13d[c][o]);
        a0 = a1; a1 = anext;
    }

    // epilogue: write own tile + mirror tile (transposed via shared), 8 o/round
    bool diagblk = (Ti == Tj);
    float2* po = (float2*)out + (size_t)b * OO * NN * NN;
    #pragma unroll
    for (int half = 0; half < 2; half++) {
        __syncthreads();
        #pragma unroll
        for (int q = 0; q < 8; q++) Ts[q][i][j] = unpack2(acc64[half*8 + q]);
        __syncthreads();
        #pragma unroll
        for (int q = 0; q < 8; q++) {
            int o = half*8 + q;
            float2 av = unpack2(acc64[o]);
            float2 tg = Ts[q][j][i];            // value at transposed position
            float2* pout = po + (size_t)o * NN * NN;

            float2 r1;
            r1.x = av.x + bR1[o][j].x + bC1[o][i].x;
            r1.y = av.y + bR1[o][j].y + bC1[o][i].y;
            if (diagblk && i == j) {
                r1.x += hsh[o].x + ddsh[o][i].x;
                r1.y += hsh[o].y + ddsh[o][i].y;
            }
            pout[(size_t)gi * NN + gj] = r1;

            if (!diagblk) {
                float2 r2;
                r2.x = tg.x + bR2[o][j].x + bC2[o][i].x;
                r2.y = tg.y + bR2[o][j].y + bC2[o][i].y;
                pout[(size_t)mi * NN + mj] = r2;
            }
        }
    }
}

// ---------------------------------------------------------------------------
extern "C" void kernel_launch(void* const* d_in, const int* in_sizes, int n_in,
                              void* d_out, int out_size)
{
    const float* in = (const float*)d_in[0];   // (B,C,N,N,2) fp32
    const float* W  = (const float*)d_in[1];   // (C,O,15)    fp32
    float* out = (float*)d_out;                // (B,O,N,N,2) fp32

    reduce_slice_kernel<<<BB * CC * NSL, 256>>>(in);
    combine_kernel     <<<BB * CC, 256>>>();
    mix_kernel         <<<BB * OO, 256>>>(W);
    dim3 g(NPAIRS, BB);                        // x=tile pair (Ti<=Tj), y=b
    main_kernel        <<<g, 256>>>(in, W, out);
}

// round 9
// speedup vs baseline: 1.1341x; 1.0193x over previous
#include <cuda_runtime.h>
#include <cuda_bf16.h>

#define BB 16
#define CC 16
#define OO 16
#define NN 256
#define NPAIRS 136   // 16*17/2 tile pairs (Ti <= Tj)
#define NSL 16       // row-slices per (b,c) plane in the reduce pass
#define SROWS (NN/NSL)   // 16 rows per slice

// Scratch (no allocations allowed -> __device__ globals)
__device__ float d_rowsum [BB*CC*NN*2];
__device__ float d_colsum [BB*CC*NN*2];
__device__ float d_diag   [BB*CC*NN*2];
__device__ float d_colpart[BB*CC*NSL*NN*2];   // per-slice column partials (8 MB)
__device__ float d_v1     [BB*CC*2];
__device__ float d_Dd     [BB*OO*NN*2];
__device__ float d_Rt     [BB*OO*NN*2];
__device__ float d_Ct     [BB*OO*NN*2];
__device__ float d_GH     [BB*OO*4];

// packed f32x2 FMA (Blackwell; ptxas won't auto-fuse from C++)
__device__ __forceinline__ void ffma2(unsigned long long& acc,
                                      unsigned long long s,
                                      unsigned long long w) {
    asm("fma.rn.f32x2 %0, %1, %2, %0;" : "+l"(acc) : "l"(s), "l"(w));
}
__device__ __forceinline__ unsigned long long pack2(float x, float y) {
    unsigned long long r;
    asm("mov.b64 %0, {%1, %2};" : "=l"(r) : "f"(x), "f"(y));
    return r;
}
__device__ __forceinline__ float2 unpack2(unsigned long long v) {
    float2 r;
    asm("mov.b64 {%0, %1}, %2;" : "=f"(r.x), "=f"(r.y) : "l"(v));
    return r;
}

// ---------------------------------------------------------------------------
// Phase 1a: each block reduces a 16-row slice of one (b,c) plane.
// Loads stream (no shfl chains in the loop); row sums deferred to shared.
// grid = 4096 blocks for deep latency hiding.
// ---------------------------------------------------------------------------
__global__ __launch_bounds__(256) void reduce_slice_kernel(const float* __restrict__ in)
{
    int bc = blockIdx.x / NSL;                 // b*CC + c
    int sl = blockIdx.x % NSL;
    int base = sl * SROWS;                     // first row of this slice
    const float* pbase = in + (size_t)bc * NN * NN * 2;
    int tid = threadIdx.x, w = tid >> 5, l = tid & 31;

    __shared__ float2 colsh[NN];
    __shared__ float  rowx[SROWS][33];         // per-lane row partials (padded)
    __shared__ float  rowy[SROWS][33];
    __shared__ float2 diagsh[SROWS];

    colsh[tid] = make_float2(0.f, 0.f);
    __syncthreads();

    float2 colacc[8];
    #pragma unroll
    for (int q = 0; q < 8; q++) colacc[q] = make_float2(0.f, 0.f);

    // warp w handles rows {base+w, base+w+8}
    #pragma unroll
    for (int r = 0; r < SROWS / 8; r++) {
        int i = base + w + r * 8;
        const float4* row = (const float4*)(pbase + (size_t)i * NN * 2);
        float rx = 0.f, ry = 0.f;
        #pragma unroll
        for (int s = 0; s < 4; s++) {
            float4 v = row[s * 32 + l];             // columns s*64+2l, s*64+2l+1
            colacc[2*s].x   += v.x; colacc[2*s].y   += v.y;
            colacc[2*s+1].x += v.z; colacc[2*s+1].y += v.w;
            rx += v.x + v.z;  ry += v.y + v.w;
            int jb = s * 64 + 2 * l;
            if (i == jb)        diagsh[i - base] = make_float2(v.x, v.y);
            else if (i == jb+1) diagsh[i - base] = make_float2(v.z, v.w);
        }
        rowx[w + r*8][l] = rx;                      // defer row reduction
        rowy[w + r*8][l] = ry;
    }

    // column partials -> shared (distinct addresses within a warp)
    #pragma unroll
    for (int s = 0; s < 4; s++) {
        int j0 = s * 64 + 2 * l;
        atomicAdd(&colsh[j0].x,   colacc[2*s].x);
        atomicAdd(&colsh[j0].y,   colacc[2*s].y);
        atomicAdd(&colsh[j0+1].x, colacc[2*s+1].x);
        atomicAdd(&colsh[j0+1].y, colacc[2*s+1].y);
    }
    __syncthreads();

    // coalesced global writes
    ((float2*)d_colpart)[(size_t)blockIdx.x * NN + tid] = colsh[tid];
    if (tid < SROWS) {                              // row sums: thread t owns row t
        float sx = 0.f, sy = 0.f;
        #pragma unroll
        for (int k = 0; k < 32; k++) { sx += rowx[tid][k]; sy += rowy[tid][k]; }
        ((float2*)d_rowsum)[(size_t)bc * NN + base + tid] = make_float2(sx, sy);
        ((float2*)d_diag)  [(size_t)bc * NN + base + tid] = diagsh[tid];
    }
}

// ---------------------------------------------------------------------------
// Phase 1b: per (b,c) combine the NSL column partials; v1 = diag_mean + total,
// where total = sum of colsum.
// ---------------------------------------------------------------------------
__global__ __launch_bounds__(256) void combine_kernel()
{
    int bc = blockIdx.x;
    int tid = threadIdx.x;

    float2 cs = make_float2(0.f, 0.f);
    #pragma unroll
    for (int sl = 0; sl < NSL; sl++) {
        float2 p = ((const float2*)d_colpart)[(size_t)(bc * NSL + sl) * NN + tid];
        cs.x += p.x; cs.y += p.y;
    }
    ((float2*)d_colsum)[(size_t)bc * NN + tid] = cs;

    __shared__ float2 red[256];
    __shared__ float2 totsave;

    // total = sum over columns of colsum
    red[tid] = cs;
    __syncthreads();
    #pragma unroll
    for (int s = 128; s > 0; s >>= 1) {
        if (tid < s) { red[tid].x += red[tid + s].x; red[tid].y += red[tid + s].y; }
        __syncthreads();
    }
    if (tid == 0) totsave = red[0];
    __syncthreads();

    // diag sum
    red[tid] = ((const float2*)d_diag)[(size_t)bc * NN + tid];
    __syncthreads();
    #pragma unroll
    for (int s = 128; s > 0; s >>= 1) {
        if (tid < s) { red[tid].x += red[tid + s].x; red[tid].y += red[tid + s].y; }
        __syncthreads();
    }
    if (tid == 0) {
        d_v1[bc*2+0] = red[0].x * (1.f / NN) + totsave.x;
        d_v1[bc*2+1] = red[0].y * (1.f / NN) + totsave.y;
    }
}

// ---------------------------------------------------------------------------
// Phase 2: per (b,o) mix the reduced vectors over C with weight slots 0..12.
// ---------------------------------------------------------------------------
__global__ __launch_bounds__(256) void mix_kernel(const float* __restrict__ W)
{
    int bo = blockIdx.x; int b = bo >> 4, o = bo & 15;
    int m = threadIdx.x;

    __shared__ float ws[CC][15];
    if (m < CC * 15) { int c = m / 15, s = m % 15; ws[c][s] = W[(c*OO + o)*15 + s]; }
    __syncthreads();

    const float2* dgp = (const float2*)d_diag   + (size_t)b * CC * NN + m;
    const float2* csp = (const float2*)d_colsum + (size_t)b * CC * NN + m;
    const float2* rsp = (const float2*)d_rowsum + (size_t)b * CC * NN + m;

    float2 dacc = make_float2(0.f,0.f), racc = make_float2(0.f,0.f), cacc = make_float2(0.f,0.f);
    #pragma unroll
    for (int c = 0; c < CC; c++) {
        float2 dg = dgp[c * NN];
        float2 cs = csp[c * NN];
        float2 rs = rsp[c * NN];
        float w4 = ws[c][4],  w5 = ws[c][5],  w6 = ws[c][6];
        float w7 = ws[c][7],  w8 = ws[c][8],  w9 = ws[c][9];
        float wA = ws[c][10], wB = ws[c][11], wD = ws[c][12];
        dacc.x += w4*dg.x + w7*cs.x + wA*rs.x;  dacc.y += w4*dg.y + w7*cs.y + wA*rs.y;
        racc.x += w5*dg.x + w8*cs.x + wB*rs.x;  racc.y += w5*dg.y + w8*cs.y + wB*rs.y;
        cacc.x += w6*dg.x + w9*cs.x + wD*rs.x;  cacc.y += w6*dg.y + w9*cs.y + wD*rs.y;
    }
    ((float2*)d_Dd)[(size_t)bo * NN + m] = dacc;
    ((float2*)d_Rt)[(size_t)bo * NN + m] = racc;
    ((float2*)d_Ct)[(size_t)bo * NN + m] = cacc;

    if (m == 0) {
        float gx = 0.f, gy = 0.f, hx = 0.f, hy = 0.f;
        #pragma unroll
        for (int c = 0; c < CC; c++) {
            float vx = d_v1[(b*CC + c)*2], vy = d_v1[(b*CC + c)*2 + 1];
            gx += ws[c][0]*vx; gy += ws[c][0]*vy;
            hx += ws[c][1]*vx; hy += ws[c][1]*vy;
        }
        d_GH[bo*4+0] = gx; d_GH[bo*4+1] = gy; d_GH[bo*4+2] = hx; d_GH[bo*4+3] = hy;
    }
}

// ---------------------------------------------------------------------------
// Phase 3: main pass over compact tile-pair grid (Ti<=Tj). Symmetric W13 mix
// serves both (Ti,Tj) and (Tj,Ti). ALL 16 mirror tiles staged to shared with
// one barrier, then a barrier-free compute loop (LDS + packed f32x2 FMA);
// own-tile A values stream in two 8-deep load batches. Epilogue reuses the
// stage buffer for the transpose.
// ---------------------------------------------------------------------------
__global__ __launch_bounds__(256, 3) void main_kernel(const float* __restrict__ in,
                                                      const float* __restrict__ W,
                                                      float* __restrict__ out)
{
    // unrank linear pair index -> (Ti, Tj) with Ti <= Tj
    int t = blockIdx.x, b = blockIdx.y;
    int Ti = 0;
    while (t >= 16 - Ti) { t -= 16 - Ti; Ti++; }
    int Tj = Ti + t;

    int tid = threadIdx.x;
    int i = tid >> 4, j = tid & 15;

    __shared__ float2 Bs[CC][16][17];       // all mirror tiles (34 KB); reused as Ts
    __shared__ unsigned long long w13d[CC][OO];   // (w,w) packed
    __shared__ float2 bR1[OO][16], bC1[OO][16], bR2[OO][16], bC2[OO][16];
    __shared__ float2 hsh[OO];
    __shared__ float2 ddsh[OO][16];

    int gi = Ti*16 + i, gj = Tj*16 + j;
    int mi = Tj*16 + i, mj = Ti*16 + j;     // mirror-tile coordinates
    const float2* inb = (const float2*)in + (size_t)b * CC * NN * NN;
    size_t moff = (size_t)mi * NN + mj;
    size_t goff = (size_t)gi * NN + gj;

    // stage ALL mirror tiles (16 independent coalesced loads -> deep MLP)
    #pragma unroll
    for (int c = 0; c < CC; c++)
        Bs[c][i][j] = inb[(size_t)c * NN * NN + moff];

    {   // weights, duplicated into f32x2 lanes
        int c = tid >> 4, o = tid & 15;
        float wv = W[(c*OO + o)*15 + 13];
        w13d[c][o] = pack2(wv, wv);
    }
    {   // bias tiles; fold g (uniform per o) into the row-bias tiles
        int o = tid >> 4, x = tid & 15;
        float2 g = make_float2(d_GH[(b*OO + o)*4], d_GH[(b*OO + o)*4 + 1]);
        const float2* Rt = (const float2*)d_Rt + (size_t)(b*OO + o) * NN;
        const float2* Ct = (const float2*)d_Ct + (size_t)(b*OO + o) * NN;
        float2 r1v = Rt[Tj*16 + x], r2v = Rt[Ti*16 + x];
        bR1[o][x] = make_float2(r1v.x + g.x, r1v.y + g.y);   // Rtot[gj]+g (own tile)
        bC1[o][x] = Ct[Ti*16 + x];                            // Ctot[gi] (own tile)
        bR2[o][x] = make_float2(r2v.x + g.x, r2v.y + g.y);   // mirror tile
        bC2[o][x] = Ct[Tj*16 + x];
        if (Ti == Tj) {
            const float2* Dd = (const float2*)d_Dd + (size_t)(b*OO + o) * NN;
            ddsh[o][x] = Dd[Ti*16 + x];
        }
        if (tid < OO)
            hsh[tid] = make_float2(d_GH[(b*OO + tid)*4 + 2], d_GH[(b*OO + tid)*4 + 3]);
    }

    __syncthreads();                        // single mainloop barrier

    unsigned long long acc64[OO];
    #pragma unroll
    for (int o = 0; o < OO; o++) acc64[o] = 0ULL;

    // two 8-deep batches of own-tile loads; compute loop has no barriers
    #pragma unroll
    for (int half = 0; half < 2; half++) {
        float2 a[8];
        #pragma unroll
        for (int q = 0; q < 8; q++)
            a[q] = inb[(size_t)(half*8 + q) * NN * NN + goff];
        #pragma unroll
        for (int q = 0; q < 8; q++) {
            int c = half*8 + q;
            float2 bb = Bs[c][j][i];
            unsigned long long s64 = pack2(a[q].x + bb.x, a[q].y + bb.y);
            #pragma unroll
            for (int o = 0; o < OO; o++)
                ffma2(acc64[o], s64, w13d[c][o]);
        }
    }

    // epilogue: write own tile + mirror tile (transposed via reused Bs), 8 o/round
    bool diagblk = (Ti == Tj);
    float2* po = (float2*)out + (size_t)b * OO * NN * NN;
    #pragma unroll
    for (int half = 0; half < 2; half++) {
        __syncthreads();
        #pragma unroll
        for (int q = 0; q < 8; q++) Bs[q][i][j] = unpack2(acc64[half*8 + q]);
        __syncthreads();
        #pragma unroll
        for (int q = 0; q < 8; q++) {
            int o = half*8 + q;
            float2 av = unpack2(acc64[o]);
            float2 tg = Bs[q][j][i];            // value at transposed position
            float2* pout = po + (size_t)o * NN * NN;

            float2 r1;
            r1.x = av.x + bR1[o][j].x + bC1[o][i].x;
            r1.y = av.y + bR1[o][j].y + bC1[o][i].y;
            if (diagblk && i == j) {
                r1.x += hsh[o].x + ddsh[o][i].x;
                r1.y += hsh[o].y + ddsh[o][i].y;
            }
            pout[goff] = r1;

            if (!diagblk) {
                float2 r2;
                r2.x = tg.x + bR2[o][j].x + bC2[o][i].x;
                r2.y = tg.y + bR2[o][j].y + bC2[o][i].y;
                pout[moff] = r2;
            }
        }
    }
}

// ---------------------------------------------------------------------------
extern "C" void kernel_launch(void* const* d_in, const int* in_sizes, int n_in,
                              void* d_out, int out_size)
{
    const float* in = (const float*)d_in[0];   // (B,C,N,N,2) fp32
    const float* W  = (const float*)d_in[1];   // (C,O,15)    fp32
    float* out = (float*)d_out;                // (B,O,N,N,2) fp32

    reduce_slice_kernel<<<BB * CC * NSL, 256>>>(in);
    combine_kernel     <<<BB * CC, 256>>>();
    mix_kernel         <<<BB * OO, 256>>>(W);
    dim3 g(NPAIRS, BB);                        // x=tile pair (Ti<=Tj), y=b
    main_kernel        <<<g, 256>>>(in, W, out);
}